// round 2
// baseline (speedup 1.0000x reference)
#include <cuda_runtime.h>

// GCBFSafetyLayer: the reference QP projection uses A = L_g_h = zeros,
// so every per-constraint update is gated off by (nrm > 1e-6) == false.
// safe_action == raw_action exactly. Fastest correct kernel = minimal copy.
//
// Inputs (metadata order): positions, velocities, obstacles, raw_action.
// Output: B*N*D = 8192 float32 = 2048 float4 = raw_action.

// Fast path: exactly 2048 float4s, one block, 8 per thread, branchless.
__global__ void __launch_bounds__(256, 1)
copy_8192_kernel(const float4* __restrict__ src, float4* __restrict__ dst) {
    int t = threadIdx.x;
#pragma unroll
    for (int i = 0; i < 8; i++) {
        dst[t + i * 256] = src[t + i * 256];
    }
}

// Generic fallback (any size), scalar grid-stride.
__global__ void copy_generic_kernel(const float* __restrict__ src,
                                    float* __restrict__ dst, int n) {
    int i = blockIdx.x * blockDim.x + threadIdx.x;
    if (i < n) dst[i] = src[i];
}

extern "C" void kernel_launch(void* const* d_in, const int* in_sizes, int n_in,
                              void* d_out, int out_size) {
    const float* raw_action = (const float*)d_in[3];
    float* out = (float*)d_out;

    if (out_size == 8192) {
        copy_8192_kernel<<<1, 256>>>((const float4*)raw_action, (float4*)out);
    } else {
        int threads = 256;
        int blocks = (out_size + threads - 1) / threads;
        copy_generic_kernel<<<blocks, threads>>>(raw_action, out, out_size);
    }
}

// round 3
// speedup vs baseline: 1.3442x; 1.3442x over previous
#include <cuda_runtime.h>

// GCBFSafetyLayer: reference QP projection uses A = L_g_h = zeros, so every
// update is gated off by (nrm > 1e-6) == false; safe_action == raw_action
// exactly (bit-identical). Optimal kernel = minimal single-launch copy.
//
// R2 post-mortem: grid=1 regressed (single SM's L1tex queue serializes the
// round-trip). Best measured shape is grid=8 x 256 threads, 1 float4/thread.
// This round: identical shape, branchless (exact-size dispatch on host).

__global__ void __launch_bounds__(256, 1)
copy_exact_kernel(const float4* __restrict__ src, float4* __restrict__ dst) {
    int i = blockIdx.x * blockDim.x + threadIdx.x;
    dst[i] = src[i];
}

// Generic fallback for unexpected sizes.
__global__ void copy_generic_kernel(const float* __restrict__ src,
                                    float* __restrict__ dst, int n) {
    int i = blockIdx.x * blockDim.x + threadIdx.x;
    if (i < n) dst[i] = src[i];
}

extern "C" void kernel_launch(void* const* d_in, const int* in_sizes, int n_in,
                              void* d_out, int out_size) {
    const float* raw_action = (const float*)d_in[3];
    float* out = (float*)d_out;

    if ((out_size & 1023) == 0) {
        // out_size multiple of 1024 floats: exact grid of (out_size/1024)
        // blocks, 256 threads, one float4 each. For 8192 -> grid=8.
        int blocks = out_size / 1024;
        copy_exact_kernel<<<blocks, 256>>>((const float4*)raw_action,
                                           (float4*)out);
    } else {
        int threads = 256;
        int blocks = (out_size + threads - 1) / threads;
        copy_generic_kernel<<<blocks, threads>>>(raw_action, out, out_size);
    }
}

// round 4
// speedup vs baseline: 1.4476x; 1.0769x over previous
#include <cuda_runtime.h>

// GCBFSafetyLayer: reference QP projection uses A = L_g_h = zeros, so every
// per-constraint update is gated off by (nrm > 1e-6) == false;
// safe_action == raw_action exactly (bit-identical). Optimal kernel is a
// minimal single-launch device copy of d_in[3] -> d_out.
//
// Measured so far (kernel time): grid=8x256 w/ bounds check 3.55us,
// grid=1x256 unrolled 4.35us (single-SM L1tex queue serialization),
// grid=8x256 branchless 3.90us. Deltas among grid>=8 variants are noise.
// This round: 16 blocks x 128 threads, 1 float4/thread — halves per-SM
// sector queue depth, all blocks in wave-1.

__global__ void __launch_bounds__(128, 1)
copy_exact_kernel(const float4* __restrict__ src, float4* __restrict__ dst) {
    int i = blockIdx.x * blockDim.x + threadIdx.x;
    dst[i] = src[i];
}

// Generic fallback for unexpected sizes.
__global__ void copy_generic_kernel(const float* __restrict__ src,
                                    float* __restrict__ dst, int n) {
    int i = blockIdx.x * blockDim.x + threadIdx.x;
    if (i < n) dst[i] = src[i];
}

extern "C" void kernel_launch(void* const* d_in, const int* in_sizes, int n_in,
                              void* d_out, int out_size) {
    const float* raw_action = (const float*)d_in[3];
    float* out = (float*)d_out;

    if ((out_size & 511) == 0) {
        // Multiple of 512 floats: grid = out_size/512 blocks of 128 threads,
        // one float4 per thread. For 8192 floats -> grid=16.
        int blocks = out_size / 512;
        copy_exact_kernel<<<blocks, 128>>>((const float4*)raw_action,
                                           (float4*)out);
    } else {
        int threads = 256;
        int blocks = (out_size + threads - 1) / threads;
        copy_generic_kernel<<<blocks, threads>>>(raw_action, out, out_size);
    }
}